// round 11
// baseline (speedup 1.0000x reference)
#include <cuda_runtime.h>
#include <cstdint>

#define BS 4
#define SQ 1024
#define CH 64
#define UN 32
#define TSPAN 72
#define GRID (BS * 128)

__device__ float g_k[BS * SQ * UN];
__device__ unsigned g_flag[GRID];   // monotonic; +9 per block per launch

__device__ __forceinline__ float htanh(float x) {
    float y;
    asm("tanh.approx.f32 %0, %1;" : "=f"(y) : "f"(x));
    return y;
}
__device__ __forceinline__ uint64_t pack2(float lo, float hi) {
    uint64_t d;
    asm("mov.b64 %0, {%1,%2};" : "=l"(d) : "f"(lo), "f"(hi));
    return d;
}
__device__ __forceinline__ void unpack2(uint64_t d, float& lo, float& hi) {
    asm("mov.b64 {%0,%1}, %2;" : "=f"(lo), "=f"(hi) : "l"(d));
}
__device__ __forceinline__ uint64_t fma2(uint64_t a, uint64_t b, uint64_t c) {
    uint64_t d;
    asm("fma.rn.f32x2 %0, %1, %2, %3;" : "=l"(d) : "l"(a), "l"(b), "l"(c));
    return d;
}

// shared pool (floats)
#define OFF_XTS  0                    // xts [72][68] = 4896
#define OFF_U1   4896                 // ph1: wts[32][68]+wxs[32][68]=4352
                                      // ph2: ks[72][36]=2592 + vs 2208 = 4800
#define OFF_QS   (4896 + 4800)        // qs [8][32] = 256
#define OFF_AS   (OFF_QS + 256)       // a_s [8][64] = 512
#define OFF_WAS  (OFF_AS + 512)       // 32
#define OFF_SUM  (OFF_WAS + 32)       // 16
#define SMEM_FLOATS (OFF_SUM + 16)

__global__ __launch_bounds__(512, 4) void fused_kernel(
    const float* __restrict__ x,
    const float* __restrict__ Wt,
    const float* __restrict__ Wx,
    const float* __restrict__ bh,
    const float* __restrict__ wa,
    float* __restrict__ vout,
    float* __restrict__ aout)
{
    __shared__ __align__(16) float pool[SMEM_FLOATS];

    float* xts  = pool + OFF_XTS;   // [ti][c-swizzled], stride 68
    float* qs   = pool + OFF_QS;    // [r][u]
    float* was  = pool + OFF_WAS;
    float* sumb = pool + OFF_SUM;   // [r*2+h]

    int b = blockIdx.x >> 7;
    int sblk = blockIdx.x & 127;
    int s0 = sblk << 3;
    int tid = threadIdx.x;
    int wid = tid >> 5, ln = tid & 31;
    int r = wid >> 1;               // query row in block
    int h = wid & 1;                // window half
    int s = s0 + r;
    int tlo = s0 - 32;

    // ---- top: zero-fill the ENTIRE a row (value overwrite comes after
    //      several __syncthreads -> block-fence orders same-address stores) ----
    float4 z4 = make_float4(0.f, 0.f, 0.f, 0.f);
    float4* arow = (float4*)(aout + (((size_t)b * SQ + s) << 10));
#pragma unroll
    for (int i = 0; i < 4; i++)
        arow[(h << 7) + (i << 5) + ln] = z4;

    // ---- top: one LDG wave -- w tiles + xts halo + was ----
    {
        float* wts = pool + OFF_U1;          // [u][c], stride 68
        float* wxs = wts + UN * 68;
        int u = tid >> 4, g = tid & 15;      // 512 = 32u x 16 groups
        *(float4*)&wts[u * 68 + g * 4] = ((const float4*)Wt)[tid];
        *(float4*)&wxs[u * 68 + g * 4] = ((const float4*)Wx)[tid];
        if (tid < UN) was[tid] = wa[tid];

        int cc = tid >> 3, gq = tid & 7;
        int gb = cc >> 2, clo = cc & 3;
        const float* xb = x + (size_t)b * CH * SQ + cc * SQ;
        if (sblk >= 4 && sblk <= 123) {
            const float4* xb4 = (const float4*)(xb + tlo);   // tlo % 4 == 0
#pragma unroll
            for (int f = 0; f < 3; f++) {
                int fi = gq + f * 8;
                if (fi < 18) {
                    float4 v = xb4[fi];
                    int t0 = fi << 2;
                    xts[(t0 + 0) * 68 + (((((t0 + 0) & 7) ^ gb) << 2) | clo)] = v.x;
                    xts[(t0 + 1) * 68 + (((((t0 + 1) & 7) ^ gb) << 2) | clo)] = v.y;
                    xts[(t0 + 2) * 68 + (((((t0 + 2) & 7) ^ gb) << 2) | clo)] = v.z;
                    xts[(t0 + 3) * 68 + (((((t0 + 3) & 7) ^ gb) << 2) | clo)] = v.w;
                }
            }
        } else {
#pragma unroll
            for (int p = 0; p < 9; p++) {
                int ti = p * 8 + gq;
                int tc = min(max(tlo + ti, 0), SQ - 1);
                int csw = ((gb ^ gq) << 2) | clo;   // ti&7 == gq
                xts[ti * 68 + csw] = xb[tc];
            }
        }
    }
    __syncthreads();                         // SYNC_A

    // ---- phase 1: q (warps 0-7) / k (warps 8-15), x rows from xts, f32x2 ----
    {
        const float* wts = pool + OFF_U1;
        const float* wxs = wts + UN * 68;
        int ss = wid & 7;                    // own row index
        const float* wrow = (tid < 256) ? &wts[ln * 68] : &wxs[ln * 68];
        const float4* xp = (const float4*)&xts[(32 + ss) * 68];
        uint64_t acc01 = pack2(0.f, 0.f), acc23 = pack2(0.f, 0.f);
#pragma unroll
        for (int gg = 0; gg < 16; gg++) {    // gg = stored (swizzled) group
            float4 x4 = xp[gg];
            int wg = (gg & 8) | ((gg & 7) ^ ss);   // original channel group
            float4 w4 = *(const float4*)&wrow[wg * 4];
            acc01 = fma2(pack2(x4.x, x4.y), pack2(w4.x, w4.y), acc01);
            acc23 = fma2(pack2(x4.z, x4.w), pack2(w4.z, w4.w), acc23);
        }
        float p0, p1, p2, p3;
        unpack2(acc01, p0, p1);
        unpack2(acc23, p2, p3);
        float res = (p0 + p1) + (p2 + p3);
        if (tid < 256) {
            qs[ss * 32 + ln] = res;
        } else {
            g_k[((size_t)b * SQ + s0 + ss) * UN + ln] = res + bh[ln];  // bh folded
        }
    }
    __syncthreads();                         // SYNC_B: k stored, wts free

    // ---- release + per-warp neighbor spin + ks fill (warps 0..8) ----
    float* ks = pool + OFF_U1;               // [ti][u], stride 36 (odd 16B units)
    if (wid <= 8) {
        if (ln == 0) {
            __threadfence();                 // release own k stores
            unsigned v = atomicAdd(&g_flag[blockIdx.x], 1u);
            unsigned base = v - (v % 9u);    // 9*(launchN-1)
            int owner = min(max(sblk - 4 + wid, 0), 127);
            volatile unsigned* f = (volatile unsigned*)&g_flag[(b << 7) + owner];
            while (*f <= base) { }
            __threadfence();                 // acquire
        }
        __syncwarp();
        const float4* gk4 = (const float4*)g_k;
#pragma unroll
        for (int rep = 0; rep < 2; rep++) {
            int lin = ln + (rep << 5);       // 0..63
            int ti = (wid << 3) + (lin >> 3);
            int gq = lin & 7;
            int tc = min(max(tlo + ti, 0), SQ - 1);
            *(float4*)&ks[ti * 36 + gq * 4] = gk4[((size_t)b * SQ + tc) * 8 + gq];
        }
    }
    __syncthreads();                         // SYNC_D: ks ready

    // ---- scores + softmax (no max-shift; bounded scores, eps-only error) ----
    int j = h * 32 + ln;
    int t = s - 32 + j;
    bool valid = (t >= 0) && (t < SQ);
    int ti = r + j;                          // <= 70

    const float4* kp = (const float4*)&ks[ti * 36];
    const float4* qp = (const float4*)&qs[r * 32];
    const float4* wap = (const float4*)was;
    float acc = 0.f;
#pragma unroll
    for (int g = 0; g < 8; g++) {
        float4 q4 = qp[g];
        float4 w4 = wap[g];
        float4 k4 = kp[g];
        acc = fmaf(w4.x, htanh(q4.x + k4.x), acc);
        acc = fmaf(w4.y, htanh(q4.y + k4.y), acc);
        acc = fmaf(w4.z, htanh(q4.z + k4.z), acc);
        acc = fmaf(w4.w, htanh(q4.w + k4.w), acc);
    }

    float* a_s = pool + OFF_AS;
    float e = valid ? __expf(acc) : 0.f;
    float sm = e;
#pragma unroll
    for (int o = 16; o > 0; o >>= 1) sm += __shfl_xor_sync(0xffffffffu, sm, o);
    if (ln == 0) sumb[r * 2 + h] = sm;
    a_s[(r << 6) + j] = e;                   // unnormalized (v-pass input)
    __syncthreads();                         // SYNC_E

    float inv = __fdividef(1.f, sumb[r * 2] + sumb[r * 2 + 1] + 1e-7f);

    // ---- a window write: ONE predicated scalar STG per lane (coalesced) ----
    if (valid)
        aout[(((size_t)b * SQ + s) << 10) + t] = e * inv;

    // ---- v pass: 16 c-groups x 4 j-segments per row; f32x2 accumulators ----
    float* vs = pool + OFF_U1 + 2592;        // staggered: f(pseg)=pseg*68+r*4
    {
        int q64 = tid & 63;
        int cgrp = q64 & 15;
        int jseg = q64 >> 4;
        uint64_t v01 = pack2(0.f, 0.f), v23 = pack2(0.f, 0.f);
#pragma unroll
        for (int it2 = 0; it2 < 4; it2++) {
            float4 a4 = *(const float4*)&a_s[(r << 6) + (jseg << 4) + (it2 << 2)];
            int jb = (jseg << 4) + (it2 << 2);
#pragma unroll
            for (int ee = 0; ee < 4; ee++) {
                int row = r + jb + ee;
                float av = (ee == 0) ? a4.x : (ee == 1) ? a4.y : (ee == 2) ? a4.z : a4.w;
                uint64_t avd = pack2(av, av);
                float4 x4 = *(const float4*)&xts[row * 68 + ((cgrp ^ (row & 7)) << 2)];
                v01 = fma2(pack2(x4.x, x4.y), avd, v01);
                v23 = fma2(pack2(x4.z, x4.w), avd, v23);
            }
        }
        float4 vacc;
        unpack2(v01, vacc.x, vacc.y);
        unpack2(v23, vacc.z, vacc.w);
        vacc.x *= inv; vacc.y *= inv; vacc.z *= inv; vacc.w *= inv;
        int pseg = (r << 2) + jseg;
        *(float4*)&vs[pseg * 68 + (r << 2) + (cgrp << 2)] = vacc;
    }
    __syncthreads();                         // SYNC_F

    // ---- combine 4 j-segment partials (conflict-free banks) + v write ----
    {
        int c = tid >> 3, i = tid & 7;
        int base = (i * 4) * 68 + i * 4 + c;
        float vsum = (vs[base] + vs[base + 68]) +
                     (vs[base + 136] + vs[base + 204]);
        vout[(size_t)b * CH * SQ + c * SQ + s0 + i] = vsum;
    }
}

extern "C" void kernel_launch(void* const* d_in, const int* in_sizes, int n_in,
                              void* d_out, int out_size) {
    (void)in_sizes; (void)n_in; (void)out_size;
    const float* x  = (const float*)d_in[0];
    const float* Wt = (const float*)d_in[1];
    const float* Wx = (const float*)d_in[2];
    const float* Wa = (const float*)d_in[3];
    // d_in[4] = Wa_b: cancels exactly in the softmax, unused
    const float* bh = (const float*)d_in[5];

    float* vout = (float*)d_out;                     // (B, C, S)
    float* aout = vout + (size_t)BS * CH * SQ;       // (B, S, S)

    fused_kernel<<<GRID, 512>>>(x, Wt, Wx, bh, Wa, vout, aout);
}